// round 7
// baseline (speedup 1.0000x reference)
#include <cuda_runtime.h>
#include <math.h>
#include <stdint.h>

#define NN   50000
#define EE   800000
#define IND  128
#define HIDD 256
#define OUTD 40
#define TOT  (EE + NN)
#define BN_EPS 1e-5f

// ---------------- scratch (device globals: alloc-guard compliant) ----------------
__device__ __align__(16) float g_t1[(size_t)NN * HIDD];
__device__ __align__(16) float g_t2[(size_t)NN * HIDD];
__device__ float g_dinv[NN];
__device__ int   g_deg[NN];
__device__ int   g_cnt[NN];
__device__ int   g_cur[NN];
__device__ int   g_off[NN + 1];
__device__ int   g_row[EE];
__device__ int   g_col[EE];
__device__ int   g_csr_col[TOT];
__device__ float g_csr_w[TOT];
__device__ float g_sum[HIDD];     // zero-init at load; bn_finalize re-zeroes after use
__device__ float g_sumsq[HIDD];
__device__ float g_bn_s[HIDD];
__device__ float g_bn_t[HIDD];

static inline int cdiv(int a, int b) { return (a + b - 1) / b; }

// ---------------- tf32 helpers ----------------
__device__ __forceinline__ float to_tf32(float x) {
    uint32_t u;
    asm("cvt.rna.tf32.f32 %0, %1;" : "=r"(u) : "f"(x));
    return __uint_as_float(u);
}

__device__ __forceinline__ void mma_tf32(float c[4], const uint32_t a[4], const uint32_t b[2]) {
    asm volatile(
        "mma.sync.aligned.m16n8k8.row.col.f32.tf32.tf32.f32 "
        "{%0,%1,%2,%3}, {%4,%5,%6,%7}, {%8,%9}, {%0,%1,%2,%3};\n"
        : "+f"(c[0]), "+f"(c[1]), "+f"(c[2]), "+f"(c[3])
        : "r"(a[0]), "r"(a[1]), "r"(a[2]), "r"(a[3]), "r"(b[0]), "r"(b[1]));
}

// ---------------- preprocessing (3 launches) ----------------
__global__ void k_convert_deg(const void* ei) {
    int e = blockIdx.x * blockDim.x + threadIdx.x;
    if (e >= EE) return;
    const unsigned long long* p8 = (const unsigned long long*)ei;
    bool is64 = true;
#pragma unroll
    for (int q = 0; q < 8; q++) is64 &= (p8[q] < (unsigned long long)NN);
    int r, c;
    if (is64) {
        const long long* p = (const long long*)ei;
        r = (int)p[e];
        c = (int)p[EE + e];
    } else {
        const int* p = (const int*)ei;
        r = p[e];
        c = p[EE + e];
    }
    g_row[e] = r;
    g_col[e] = c;
    atomicAdd(&g_deg[c], 1);
    atomicAdd(&g_cnt[r], 1);
}

__global__ void k_scan_dinv() {
    __shared__ int part[1024];
    int t = threadIdx.x;
    const int CH = (NN + 1023) / 1024;
    int b = t * CH;
    int e = min(NN, b + CH);
    int s = 0;
    for (int i = b; i < e; i++) {
        s += g_cnt[i] + 1;
        g_dinv[i] = rsqrtf((float)(g_deg[i] + 1));
        g_deg[i] = 0;
        g_cur[i] = 0;
    }
    part[t] = s;
    __syncthreads();
    for (int off = 1; off < 1024; off <<= 1) {
        int v = (t >= off) ? part[t - off] : 0;
        __syncthreads();
        part[t] += v;
        __syncthreads();
    }
    int pre = (t == 0) ? 0 : part[t - 1];
    for (int i = b; i < e; i++) {
        g_off[i] = pre;
        pre += g_cnt[i] + 1;
        g_cnt[i] = 0;
    }
    if (t == 1023) g_off[NN] = part[1023];
}

__global__ void k_fill() {
    int idx = blockIdx.x * blockDim.x + threadIdx.x;
    if (idx >= TOT) return;
    int r, c; float w;
    if (idx < EE) {
        r = g_row[idx];
        c = g_col[idx];
        w = g_dinv[r] * g_dinv[c];
    } else {
        r = idx - EE;
        c = r;
        float d = g_dinv[r];
        w = d * d;
    }
    int pos = g_off[r] + atomicAdd(&g_cur[r], 1);
    g_csr_col[pos] = c;
    g_csr_w[pos]   = w;
}

// ---------------- tensor-core GEMM, paired-smem layouts (LDS.64 reads) ----------------
// A smem: float2 pair of (m, m+8):  pairidx = k*68 + mq, mq=(m&7)|((m>>4)<<3), slot=(m>>3)&1
// B smem: float2 pair of (k, k+4):  pairidx = kq*68 + n, kq=(k&3)|((k>>3)<<2), slot=(k>>2)&1
// Stride 68 == 4 (mod 16) -> conflict-free LDS.64 for the mma fragment pattern.
template <bool FUSE, bool BIAS>
__global__ void __launch_bounds__(256) k_gemm_tc(
    const float* __restrict__ A, const float* __restrict__ B,
    const float* __restrict__ bias, float* __restrict__ C,
    int M, int K, int Ncols)
{
    constexpr int BM = 128, BN = 64, BK = 32;
    __shared__ float2 As2[BK * 68];   // 17408 B
    __shared__ float2 Bs2[16 * 68];   //  8704 B
    float* Af = (float*)As2;
    float* Bf = (float*)Bs2;

    const int tid  = threadIdx.x;
    const int warp = tid >> 5, lane = tid & 31;
    const int gid  = lane >> 2, tg = lane & 3;
    const int wm   = (warp & 3) * 32;
    const int wn   = (warp >> 2) * 32;
    const int bm   = blockIdx.y * BM, bn = blockIdx.x * BN;

    float c[2][4][4];
#pragma unroll
    for (int i = 0; i < 2; i++)
#pragma unroll
        for (int j = 0; j < 4; j++)
#pragma unroll
            for (int q = 0; q < 4; q++) c[i][j][q] = 0.f;

    float4 areg[4];
    float  breg[8];

    // prologue: A loads, m = idx&127 (one row per lane -> conflict-free smem writes)
#pragma unroll
    for (int r = 0; r < 4; r++) {
        int idx = tid + r * 256;
        int m = idx & 127, c4 = idx >> 7;
        int gm = bm + m;
        areg[r] = make_float4(0.f, 0.f, 0.f, 0.f);
        if (gm < M) areg[r] = *reinterpret_cast<const float4*>(A + (size_t)gm * K + c4 * 4);
    }
#pragma unroll
    for (int r = 0; r < 8; r++) {
        int idx = tid + r * 256;
        int kk = idx >> 6, n = idx & 63;
        breg[r] = (bn + n < Ncols) ? B[(size_t)kk * Ncols + bn + n] : 0.f;
    }

    for (int k0 = 0; k0 < K; k0 += BK) {
        // ---- store staged A to paired smem ----
#pragma unroll
        for (int r = 0; r < 4; r++) {
            int idx = tid + r * 256;
            int m = idx & 127, c4 = idx >> 7;
            int mq = (m & 7) | ((m >> 4) << 3);
            int mslot = (m >> 3) & 1;
            float4 v = areg[r];
            if (FUSE) {
                int gk = k0 + c4 * 4;
                v.x = fmaxf(0.f, fmaf(v.x, g_bn_s[gk + 0], g_bn_t[gk + 0]));
                v.y = fmaxf(0.f, fmaf(v.y, g_bn_s[gk + 1], g_bn_t[gk + 1]));
                v.z = fmaxf(0.f, fmaf(v.z, g_bn_s[gk + 2], g_bn_t[gk + 2]));
                v.w = fmaxf(0.f, fmaf(v.w, g_bn_s[gk + 3], g_bn_t[gk + 3]));
            }
            int kb0 = c4 * 4;
            Af[((kb0 + 0) * 68 + mq) * 2 + mslot] = to_tf32(v.x);
            Af[((kb0 + 1) * 68 + mq) * 2 + mslot] = to_tf32(v.y);
            Af[((kb0 + 2) * 68 + mq) * 2 + mslot] = to_tf32(v.z);
            Af[((kb0 + 3) * 68 + mq) * 2 + mslot] = to_tf32(v.w);
        }
        // ---- store staged B to paired smem ----
#pragma unroll
        for (int r = 0; r < 8; r++) {
            int idx = tid + r * 256;
            int kk = idx >> 6, n = idx & 63;
            int kq = (kk & 3) | ((kk >> 3) << 2);
            int kslot = (kk >> 2) & 1;
            Bf[(kq * 68 + n) * 2 + kslot] = to_tf32(breg[r]);
        }
        __syncthreads();

        // ---- prefetch next tile ----
        if (k0 + BK < K) {
            int kn = k0 + BK;
#pragma unroll
            for (int r = 0; r < 4; r++) {
                int idx = tid + r * 256;
                int m = idx & 127, c4 = idx >> 7;
                int gm = bm + m;
                areg[r] = make_float4(0.f, 0.f, 0.f, 0.f);
                if (gm < M) areg[r] = *reinterpret_cast<const float4*>(A + (size_t)gm * K + kn + c4 * 4);
            }
#pragma unroll
            for (int r = 0; r < 8; r++) {
                int idx = tid + r * 256;
                int kk = idx >> 6, n = idx & 63;
                breg[r] = (bn + n < Ncols) ? B[(size_t)(kn + kk) * Ncols + bn + n] : 0.f;
            }
        }

        // ---- compute: LDS.64 fragment loads ----
#pragma unroll
        for (int kc = 0; kc < 4; kc++) {
            int kb = kc * 8 + tg;
            int kq = tg | (kc << 2);
            uint32_t a[2][4], b[4][2];
#pragma unroll
            for (int am = 0; am < 2; am++) {
                int mr = wm + am * 16 + gid;               // (mr>>3)&1 == 0 always
                int mq = (mr & 7) | ((mr >> 4) << 3);
                float2 lo = As2[kb * 68 + mq];             // (mr,kb),(mr+8,kb)
                float2 hi = As2[(kb + 4) * 68 + mq];       // (mr,kb+4),(mr+8,kb+4)
                a[am][0] = __float_as_uint(lo.x);
                a[am][1] = __float_as_uint(lo.y);
                a[am][2] = __float_as_uint(hi.x);
                a[am][3] = __float_as_uint(hi.y);
            }
#pragma unroll
            for (int bi = 0; bi < 4; bi++) {
                int nc = wn + bi * 8 + gid;
                float2 pb = Bs2[kq * 68 + nc];             // (kb,nc),(kb+4,nc)
                b[bi][0] = __float_as_uint(pb.x);
                b[bi][1] = __float_as_uint(pb.y);
            }
#pragma unroll
            for (int am = 0; am < 2; am++)
#pragma unroll
                for (int bi = 0; bi < 4; bi++)
                    mma_tf32(c[am][bi], a[am], b[bi]);
        }
        __syncthreads();
    }

#pragma unroll
    for (int am = 0; am < 2; am++) {
#pragma unroll
        for (int bi = 0; bi < 4; bi++) {
            int row = bm + wm + am * 16 + gid;
            int col = bn + wn + bi * 8 + 2 * tg;
            float bv0 = 0.f, bv1 = 0.f;
            if (BIAS) {
                if (col < Ncols)     bv0 = bias[col];
                if (col + 1 < Ncols) bv1 = bias[col + 1];
            }
            if (row < M) {
                if (col < Ncols)     C[(size_t)row * Ncols + col]     = c[am][bi][0] + bv0;
                if (col + 1 < Ncols) C[(size_t)row * Ncols + col + 1] = c[am][bi][1] + bv1;
            }
            if (row + 8 < M) {
                if (col < Ncols)     C[(size_t)(row + 8) * Ncols + col]     = c[am][bi][2] + bv0;
                if (col + 1 < Ncols) C[(size_t)(row + 8) * Ncols + col + 1] = c[am][bi][3] + bv1;
            }
        }
    }
}

// ---------------- aggregation (1 row per block, unroll 4) ----------------
template <int F4, bool BIAS>
__global__ void __launch_bounds__(F4) k_agg_v(
    const float* __restrict__ h, const float* __restrict__ bias,
    float* __restrict__ out)
{
    const int F = F4 * 4;
    int i = blockIdx.x;
    int t = threadIdx.x;
    float4 acc = make_float4(0.f, 0.f, 0.f, 0.f);
    int p = g_off[i], end = g_off[i + 1];
    for (; p + 3 < end; p += 4) {
        int   c0 = __ldg(&g_csr_col[p]);
        int   c1 = __ldg(&g_csr_col[p + 1]);
        int   c2 = __ldg(&g_csr_col[p + 2]);
        int   c3 = __ldg(&g_csr_col[p + 3]);
        float w0 = __ldg(&g_csr_w[p]);
        float w1 = __ldg(&g_csr_w[p + 1]);
        float w2 = __ldg(&g_csr_w[p + 2]);
        float w3 = __ldg(&g_csr_w[p + 3]);
        float4 v0 = *reinterpret_cast<const float4*>(h + (size_t)c0 * F + t * 4);
        float4 v1 = *reinterpret_cast<const float4*>(h + (size_t)c1 * F + t * 4);
        float4 v2 = *reinterpret_cast<const float4*>(h + (size_t)c2 * F + t * 4);
        float4 v3 = *reinterpret_cast<const float4*>(h + (size_t)c3 * F + t * 4);
        acc.x = fmaf(w0, v0.x, fmaf(w1, v1.x, fmaf(w2, v2.x, fmaf(w3, v3.x, acc.x))));
        acc.y = fmaf(w0, v0.y, fmaf(w1, v1.y, fmaf(w2, v2.y, fmaf(w3, v3.y, acc.y))));
        acc.z = fmaf(w0, v0.z, fmaf(w1, v1.z, fmaf(w2, v2.z, fmaf(w3, v3.z, acc.z))));
        acc.w = fmaf(w0, v0.w, fmaf(w1, v1.w, fmaf(w2, v2.w, fmaf(w3, v3.w, acc.w))));
    }
    for (; p < end; p++) {
        int   c0 = __ldg(&g_csr_col[p]);
        float w0 = __ldg(&g_csr_w[p]);
        float4 v0 = *reinterpret_cast<const float4*>(h + (size_t)c0 * F + t * 4);
        acc.x = fmaf(w0, v0.x, acc.x);
        acc.y = fmaf(w0, v0.y, acc.y);
        acc.z = fmaf(w0, v0.z, acc.z);
        acc.w = fmaf(w0, v0.w, acc.w);
    }
    if (BIAS) {
        float4 b = *reinterpret_cast<const float4*>(bias + t * 4);
        acc.x += b.x; acc.y += b.y; acc.z += b.z; acc.w += b.w;
    }
    *reinterpret_cast<float4*>(out + (size_t)i * F + t * 4) = acc;
}

// ---------------- fused layer-3 aggregation + log_softmax (warp per row) ----------------
__global__ void __launch_bounds__(32) k_agg_softmax(
    const float* __restrict__ h, const float* __restrict__ bias,
    float* __restrict__ out)
{
    int i = blockIdx.x;
    int t = threadIdx.x;
    float a0 = 0.f, a1 = 0.f;
    int p = g_off[i], end = g_off[i + 1];
    for (; p + 1 < end; p += 2) {
        int   c0 = __ldg(&g_csr_col[p]);
        int   c1 = __ldg(&g_csr_col[p + 1]);
        float w0 = __ldg(&g_csr_w[p]);
        float w1 = __ldg(&g_csr_w[p + 1]);
        const float* h0 = h + (size_t)c0 * OUTD;
        const float* h1 = h + (size_t)c1 * OUTD;
        a0 = fmaf(w0, h0[t], fmaf(w1, h1[t], a0));
        if (t < 8) a1 = fmaf(w0, h0[t + 32], fmaf(w1, h1[t + 32], a1));
    }
    if (p < end) {
        int   c0 = __ldg(&g_csr_col[p]);
        float w0 = __ldg(&g_csr_w[p]);
        const float* h0 = h + (size_t)c0 * OUTD;
        a0 = fmaf(w0, h0[t], a0);
        if (t < 8) a1 = fmaf(w0, h0[t + 32], a1);
    }
    float v0 = a0 + bias[t];
    float v1 = (t < 8) ? (a1 + bias[t + 32]) : -INFINITY;
    float m = fmaxf(v0, v1);
#pragma unroll
    for (int off = 16; off > 0; off >>= 1)
        m = fmaxf(m, __shfl_xor_sync(0xFFFFFFFFu, m, off));
    float s = expf(v0 - m) + ((t < 8) ? expf(v1 - m) : 0.f);
#pragma unroll
    for (int off = 16; off > 0; off >>= 1)
        s += __shfl_xor_sync(0xFFFFFFFFu, s, off);
    float l = m + logf(s);
    out[(size_t)i * OUTD + t] = v0 - l;
    if (t < 8) out[(size_t)i * OUTD + t + 32] = v1 - l;
}

// ---------------- batchnorm stats ----------------
__global__ void __launch_bounds__(256) k_stats(const float* __restrict__ h) {
    int c = threadIdx.x;
    int rows_per_block = (NN + gridDim.x - 1) / gridDim.x;
    int r0 = blockIdx.x * rows_per_block;
    int r1 = min(NN, r0 + rows_per_block);
    float s = 0.f, ss = 0.f;
    for (int r = r0; r < r1; r++) {
        float v = h[(size_t)r * HIDD + c];
        s += v;
        ss = fmaf(v, v, ss);
    }
    atomicAdd(&g_sum[c], s);
    atomicAdd(&g_sumsq[c], ss);
}

// reads stats, computes scale/shift, then re-zeroes accumulators for next pass
__global__ void k_bn_finalize(const float* __restrict__ gamma,
                              const float* __restrict__ beta) {
    int c = threadIdx.x;
    float mu = g_sum[c] * (1.f / NN);
    float var = g_sumsq[c] * (1.f / NN) - mu * mu;
    float rstd = rsqrtf(var + BN_EPS);
    float sc = rstd * gamma[c];
    g_bn_s[c] = sc;
    g_bn_t[c] = beta[c] - mu * sc;
    g_sum[c] = 0.f;
    g_sumsq[c] = 0.f;
}

// ---------------- launch ----------------
extern "C" void kernel_launch(void* const* d_in, const int* in_sizes, int n_in,
                              void* d_out, int out_size) {
    const float* x     = (const float*)d_in[0];
    const void*  ei    = d_in[1];
    const float* W1    = (const float*)d_in[2];
    const float* b1    = (const float*)d_in[3];
    const float* W2    = (const float*)d_in[4];
    const float* b2    = (const float*)d_in[5];
    const float* W3    = (const float*)d_in[6];
    const float* b3    = (const float*)d_in[7];
    const float* gamma = (const float*)d_in[8];
    const float* beta  = (const float*)d_in[9];
    float* out = (float*)d_out;

    float *t1, *t2;
    cudaGetSymbolAddress((void**)&t1, g_t1);
    cudaGetSymbolAddress((void**)&t2, g_t2);

    // preprocessing
    k_convert_deg<<<cdiv(EE, 256), 256>>>(ei);   // 0
    k_scan_dinv<<<1, 1024>>>();                  // 1
    k_fill<<<cdiv(TOT, 256), 256>>>();           // 2

    dim3 g256(4, cdiv(NN, 128));    // Ncols=256
    dim3 g40(1, cdiv(NN, 128));     // Ncols=40

    // layer 1: agg-first (128-wide gather), GEMM with fused bias
    k_agg_v<32, false><<<NN, 32>>>(x, nullptr, t1);                        // 3
    k_gemm_tc<false, true><<<g256, 256>>>(t1, W1, b1, t2, NN, IND, HIDD);  // 4
    k_stats<<<256, HIDD>>>(t2);                                            // 5
    k_bn_finalize<<<1, HIDD>>>(gamma, beta);                               // 6

    // layer 2 (BN+ReLU fused into GEMM A-load)
    k_gemm_tc<true, false><<<g256, 256>>>(t2, W2, nullptr, t1, NN, HIDD, HIDD); // 7
    k_agg_v<64, true><<<NN, 64>>>(t1, b2, t2);                                  // 8
    k_stats<<<256, HIDD>>>(t2);                                                 // 9
    k_bn_finalize<<<1, HIDD>>>(gamma, beta);                                    // 10

    // layer 3: GEMM then fused agg+log_softmax straight to output
    k_gemm_tc<true, false><<<g40, 256>>>(t2, W3, nullptr, t1, NN, HIDD, OUTD);  // 11
    k_agg_softmax<<<NN, 32>>>(t1, b3, out);                                     // 12
}

// round 8
// speedup vs baseline: 1.0074x; 1.0074x over previous
#include <cuda_runtime.h>
#include <math.h>
#include <stdint.h>

#define NN   50000
#define EE   800000
#define IND  128
#define HIDD 256
#define OUTD 40
#define TOT  (EE + NN)
#define BN_EPS 1e-5f

// ---------------- scratch (device globals: alloc-guard compliant) ----------------
__device__ __align__(16) float g_t1[(size_t)NN * HIDD];
__device__ __align__(16) float g_t2[(size_t)NN * HIDD];
__device__ float g_dinv[NN];
__device__ int   g_deg[NN];
__device__ int   g_cnt[NN];
__device__ int   g_cur[NN];
__device__ int   g_off[NN + 1];
__device__ int   g_row[EE];
__device__ int   g_col[EE];
__device__ __align__(16) int   g_csr_col[TOT + 4];
__device__ __align__(16) float g_csr_w[TOT + 4];
__device__ float g_sum[HIDD];     // zero-init at load; bn_finalize re-zeroes after use
__device__ float g_sumsq[HIDD];
__device__ float g_bn_s[HIDD];
__device__ float g_bn_t[HIDD];

static inline int cdiv(int a, int b) { return (a + b - 1) / b; }

// ---------------- tf32 helpers ----------------
__device__ __forceinline__ float to_tf32(float x) {
    uint32_t u;
    asm("cvt.rna.tf32.f32 %0, %1;" : "=r"(u) : "f"(x));
    return __uint_as_float(u);
}

__device__ __forceinline__ void mma_tf32(float c[4], const uint32_t a[4], const uint32_t b[2]) {
    asm volatile(
        "mma.sync.aligned.m16n8k8.row.col.f32.tf32.tf32.f32 "
        "{%0,%1,%2,%3}, {%4,%5,%6,%7}, {%8,%9}, {%0,%1,%2,%3};\n"
        : "+f"(c[0]), "+f"(c[1]), "+f"(c[2]), "+f"(c[3])
        : "r"(a[0]), "r"(a[1]), "r"(a[2]), "r"(a[3]), "r"(b[0]), "r"(b[1]));
}

// ---------------- preprocessing (3 launches) ----------------
__global__ void k_convert_deg(const void* ei) {
    int e = blockIdx.x * blockDim.x + threadIdx.x;
    if (e >= EE) return;
    const unsigned long long* p8 = (const unsigned long long*)ei;
    bool is64 = true;
#pragma unroll
    for (int q = 0; q < 8; q++) is64 &= (p8[q] < (unsigned long long)NN);
    int r, c;
    if (is64) {
        const long long* p = (const long long*)ei;
        r = (int)p[e];
        c = (int)p[EE + e];
    } else {
        const int* p = (const int*)ei;
        r = p[e];
        c = p[EE + e];
    }
    g_row[e] = r;
    g_col[e] = c;
    atomicAdd(&g_deg[c], 1);
    atomicAdd(&g_cnt[r], 1);
}

__global__ void k_scan_dinv() {
    __shared__ int part[1024];
    int t = threadIdx.x;
    const int CH = (NN + 1023) / 1024;
    int b = t * CH;
    int e = min(NN, b + CH);
    int s = 0;
    for (int i = b; i < e; i++) {
        s += g_cnt[i] + 1;
        g_dinv[i] = rsqrtf((float)(g_deg[i] + 1));
        g_deg[i] = 0;
        g_cur[i] = 0;
    }
    part[t] = s;
    __syncthreads();
    for (int off = 1; off < 1024; off <<= 1) {
        int v = (t >= off) ? part[t - off] : 0;
        __syncthreads();
        part[t] += v;
        __syncthreads();
    }
    int pre = (t == 0) ? 0 : part[t - 1];
    for (int i = b; i < e; i++) {
        g_off[i] = pre;
        pre += g_cnt[i] + 1;
        g_cnt[i] = 0;
    }
    if (t == 1023) g_off[NN] = part[1023];
}

__global__ void k_fill() {
    int idx = blockIdx.x * blockDim.x + threadIdx.x;
    if (idx >= TOT) return;
    int r, c; float w;
    if (idx < EE) {
        r = g_row[idx];
        c = g_col[idx];
        w = g_dinv[r] * g_dinv[c];
    } else {
        r = idx - EE;
        c = r;
        float d = g_dinv[r];
        w = d * d;
    }
    int pos = g_off[r] + atomicAdd(&g_cur[r], 1);
    g_csr_col[pos] = c;
    g_csr_w[pos]   = w;
}

// ---------------- tensor-core GEMM, paired-smem layouts (LDS.64 reads) ----------------
template <bool FUSE, bool BIAS>
__global__ void __launch_bounds__(256) k_gemm_tc(
    const float* __restrict__ A, const float* __restrict__ B,
    const float* __restrict__ bias, float* __restrict__ C,
    int M, int K, int Ncols)
{
    constexpr int BM = 128, BN = 64, BK = 32;
    __shared__ float2 As2[BK * 68];
    __shared__ float2 Bs2[16 * 68];
    float* Af = (float*)As2;
    float* Bf = (float*)Bs2;

    const int tid  = threadIdx.x;
    const int warp = tid >> 5, lane = tid & 31;
    const int gid  = lane >> 2, tg = lane & 3;
    const int wm   = (warp & 3) * 32;
    const int wn   = (warp >> 2) * 32;
    const int bm   = blockIdx.y * BM, bn = blockIdx.x * BN;

    float c[2][4][4];
#pragma unroll
    for (int i = 0; i < 2; i++)
#pragma unroll
        for (int j = 0; j < 4; j++)
#pragma unroll
            for (int q = 0; q < 4; q++) c[i][j][q] = 0.f;

    float4 areg[4];
    float  breg[8];

#pragma unroll
    for (int r = 0; r < 4; r++) {
        int idx = tid + r * 256;
        int m = idx & 127, c4 = idx >> 7;
        int gm = bm + m;
        areg[r] = make_float4(0.f, 0.f, 0.f, 0.f);
        if (gm < M) areg[r] = *reinterpret_cast<const float4*>(A + (size_t)gm * K + c4 * 4);
    }
#pragma unroll
    for (int r = 0; r < 8; r++) {
        int idx = tid + r * 256;
        int kk = idx >> 6, n = idx & 63;
        breg[r] = (bn + n < Ncols) ? B[(size_t)kk * Ncols + bn + n] : 0.f;
    }

    for (int k0 = 0; k0 < K; k0 += BK) {
#pragma unroll
        for (int r = 0; r < 4; r++) {
            int idx = tid + r * 256;
            int m = idx & 127, c4 = idx >> 7;
            int mq = (m & 7) | ((m >> 4) << 3);
            int mslot = (m >> 3) & 1;
            float4 v = areg[r];
            if (FUSE) {
                int gk = k0 + c4 * 4;
                v.x = fmaxf(0.f, fmaf(v.x, g_bn_s[gk + 0], g_bn_t[gk + 0]));
                v.y = fmaxf(0.f, fmaf(v.y, g_bn_s[gk + 1], g_bn_t[gk + 1]));
                v.z = fmaxf(0.f, fmaf(v.z, g_bn_s[gk + 2], g_bn_t[gk + 2]));
                v.w = fmaxf(0.f, fmaf(v.w, g_bn_s[gk + 3], g_bn_t[gk + 3]));
            }
            int kb0 = c4 * 4;
            Af[((kb0 + 0) * 68 + mq) * 2 + mslot] = to_tf32(v.x);
            Af[((kb0 + 1) * 68 + mq) * 2 + mslot] = to_tf32(v.y);
            Af[((kb0 + 2) * 68 + mq) * 2 + mslot] = to_tf32(v.z);
            Af[((kb0 + 3) * 68 + mq) * 2 + mslot] = to_tf32(v.w);
        }
#pragma unroll
        for (int r = 0; r < 8; r++) {
            int idx = tid + r * 256;
            int kk = idx >> 6, n = idx & 63;
            int kq = (kk & 3) | ((kk >> 3) << 2);
            int kslot = (kk >> 2) & 1;
            Bf[(kq * 68 + n) * 2 + kslot] = to_tf32(breg[r]);
        }
        __syncthreads();

        if (k0 + BK < K) {
            int kn = k0 + BK;
#pragma unroll
            for (int r = 0; r < 4; r++) {
                int idx = tid + r * 256;
                int m = idx & 127, c4 = idx >> 7;
                int gm = bm + m;
                areg[r] = make_float4(0.f, 0.f, 0.f, 0.f);
                if (gm < M) areg[r] = *reinterpret_cast<const float4*>(A + (size_t)gm * K + kn + c4 * 4);
            }
#pragma unroll
            for (int r = 0; r < 8; r++) {
                int idx = tid + r * 256;
                int kk = idx >> 6, n = idx & 63;
                breg[r] = (bn + n < Ncols) ? B[(size_t)(kn + kk) * Ncols + bn + n] : 0.f;
            }
        }

#pragma unroll
        for (int kc = 0; kc < 4; kc++) {
            int kb = kc * 8 + tg;
            int kq = tg | (kc << 2);
            uint32_t a[2][4], b[4][2];
#pragma unroll
            for (int am = 0; am < 2; am++) {
                int mr = wm + am * 16 + gid;
                int mq = (mr & 7) | ((mr >> 4) << 3);
                float2 lo = As2[kb * 68 + mq];
                float2 hi = As2[(kb + 4) * 68 + mq];
                a[am][0] = __float_as_uint(lo.x);
                a[am][1] = __float_as_uint(lo.y);
                a[am][2] = __float_as_uint(hi.x);
                a[am][3] = __float_as_uint(hi.y);
            }
#pragma unroll
            for (int bi = 0; bi < 4; bi++) {
                int nc = wn + bi * 8 + gid;
                float2 pb = Bs2[kq * 68 + nc];
                b[bi][0] = __float_as_uint(pb.x);
                b[bi][1] = __float_as_uint(pb.y);
            }
#pragma unroll
            for (int am = 0; am < 2; am++)
#pragma unroll
                for (int bi = 0; bi < 4; bi++)
                    mma_tf32(c[am][bi], a[am], b[bi]);
        }
        __syncthreads();
    }

#pragma unroll
    for (int am = 0; am < 2; am++) {
#pragma unroll
        for (int bi = 0; bi < 4; bi++) {
            int row = bm + wm + am * 16 + gid;
            int col = bn + wn + bi * 8 + 2 * tg;
            float bv0 = 0.f, bv1 = 0.f;
            if (BIAS) {
                if (col < Ncols)     bv0 = bias[col];
                if (col + 1 < Ncols) bv1 = bias[col + 1];
            }
            if (row < M) {
                if (col < Ncols)     C[(size_t)row * Ncols + col]     = c[am][bi][0] + bv0;
                if (col + 1 < Ncols) C[(size_t)row * Ncols + col + 1] = c[am][bi][1] + bv1;
            }
            if (row + 8 < M) {
                if (col < Ncols)     C[(size_t)(row + 8) * Ncols + col]     = c[am][bi][2] + bv0;
                if (col + 1 < Ncols) C[(size_t)(row + 8) * Ncols + col + 1] = c[am][bi][3] + bv1;
            }
        }
    }
}

// ---------------- aggregation: multi-row blocks + vectorized CSR metadata ----------------
// RPB rows per block, F4 float4-lanes per row. Align p to 4, then int4/float4 metadata loads.
template <int F4, int RPB, bool BIAS>
__global__ void __launch_bounds__(F4 * RPB) k_agg_v(
    const float* __restrict__ h, const float* __restrict__ bias,
    float* __restrict__ out)
{
    const int F = F4 * 4;
    int i = blockIdx.x * RPB + threadIdx.x / F4;
    int t = threadIdx.x % F4;
    if (RPB > 1 && i >= NN) return;
    float4 acc = make_float4(0.f, 0.f, 0.f, 0.f);
    int p = g_off[i], end = g_off[i + 1];

    // head: advance to 4-aligned p
    while (p < end && (p & 3)) {
        int   c0 = __ldg(&g_csr_col[p]);
        float w0 = __ldg(&g_csr_w[p]);
        float4 v0 = *reinterpret_cast<const float4*>(h + (size_t)c0 * F + t * 4);
        acc.x = fmaf(w0, v0.x, acc.x);
        acc.y = fmaf(w0, v0.y, acc.y);
        acc.z = fmaf(w0, v0.z, acc.z);
        acc.w = fmaf(w0, v0.w, acc.w);
        p++;
    }
    // vector body
    for (; p + 3 < end; p += 4) {
        int4   cv = *reinterpret_cast<const int4*>(&g_csr_col[p]);
        float4 wv = *reinterpret_cast<const float4*>(&g_csr_w[p]);
        float4 v0 = *reinterpret_cast<const float4*>(h + (size_t)cv.x * F + t * 4);
        float4 v1 = *reinterpret_cast<const float4*>(h + (size_t)cv.y * F + t * 4);
        float4 v2 = *reinterpret_cast<const float4*>(h + (size_t)cv.z * F + t * 4);
        float4 v3 = *reinterpret_cast<const float4*>(h + (size_t)cv.w * F + t * 4);
        acc.x = fmaf(wv.x, v0.x, fmaf(wv.y, v1.x, fmaf(wv.z, v2.x, fmaf(wv.w, v3.x, acc.x))));
        acc.y = fmaf(wv.x, v0.y, fmaf(wv.y, v1.y, fmaf(wv.z, v2.y, fmaf(wv.w, v3.y, acc.y))));
        acc.z = fmaf(wv.x, v0.z, fmaf(wv.y, v1.z, fmaf(wv.z, v2.z, fmaf(wv.w, v3.z, acc.z))));
        acc.w = fmaf(wv.x, v0.w, fmaf(wv.y, v1.w, fmaf(wv.z, v2.w, fmaf(wv.w, v3.w, acc.w))));
    }
    // tail
    for (; p < end; p++) {
        int   c0 = __ldg(&g_csr_col[p]);
        float w0 = __ldg(&g_csr_w[p]);
        float4 v0 = *reinterpret_cast<const float4*>(h + (size_t)c0 * F + t * 4);
        acc.x = fmaf(w0, v0.x, acc.x);
        acc.y = fmaf(w0, v0.y, acc.y);
        acc.z = fmaf(w0, v0.z, acc.z);
        acc.w = fmaf(w0, v0.w, acc.w);
    }
    if (BIAS) {
        float4 b = *reinterpret_cast<const float4*>(bias + t * 4);
        acc.x += b.x; acc.y += b.y; acc.z += b.z; acc.w += b.w;
    }
    *reinterpret_cast<float4*>(out + (size_t)i * F + t * 4) = acc;
}

// ---------------- fused layer-3 agg + log_softmax (4 warps/block, warp per row) ----------------
__global__ void __launch_bounds__(128) k_agg_softmax(
    const float* __restrict__ h, const float* __restrict__ bias,
    float* __restrict__ out)
{
    int i = blockIdx.x * 4 + (threadIdx.x >> 5);
    int t = threadIdx.x & 31;
    if (i >= NN) return;
    float a0 = 0.f, a1 = 0.f;
    int p = g_off[i], end = g_off[i + 1];
    for (; p + 1 < end; p += 2) {
        int   c0 = __ldg(&g_csr_col[p]);
        int   c1 = __ldg(&g_csr_col[p + 1]);
        float w0 = __ldg(&g_csr_w[p]);
        float w1 = __ldg(&g_csr_w[p + 1]);
        const float* h0 = h + (size_t)c0 * OUTD;
        const float* h1 = h + (size_t)c1 * OUTD;
        a0 = fmaf(w0, h0[t], fmaf(w1, h1[t], a0));
        if (t < 8) a1 = fmaf(w0, h0[t + 32], fmaf(w1, h1[t + 32], a1));
    }
    if (p < end) {
        int   c0 = __ldg(&g_csr_col[p]);
        float w0 = __ldg(&g_csr_w[p]);
        const float* h0 = h + (size_t)c0 * OUTD;
        a0 = fmaf(w0, h0[t], a0);
        if (t < 8) a1 = fmaf(w0, h0[t + 32], a1);
    }
    float v0 = a0 + bias[t];
    float v1 = (t < 8) ? (a1 + bias[t + 32]) : -INFINITY;
    float m = fmaxf(v0, v1);
#pragma unroll
    for (int off = 16; off > 0; off >>= 1)
        m = fmaxf(m, __shfl_xor_sync(0xFFFFFFFFu, m, off));
    float s = expf(v0 - m) + ((t < 8) ? expf(v1 - m) : 0.f);
#pragma unroll
    for (int off = 16; off > 0; off >>= 1)
        s += __shfl_xor_sync(0xFFFFFFFFu, s, off);
    float l = m + logf(s);
    out[(size_t)i * OUTD + t] = v0 - l;
    if (t < 8) out[(size_t)i * OUTD + t + 32] = v1 - l;
}

// ---------------- batchnorm stats ----------------
__global__ void __launch_bounds__(256) k_stats(const float* __restrict__ h) {
    int c = threadIdx.x;
    int rows_per_block = (NN + gridDim.x - 1) / gridDim.x;
    int r0 = blockIdx.x * rows_per_block;
    int r1 = min(NN, r0 + rows_per_block);
    float s = 0.f, ss = 0.f;
    for (int r = r0; r < r1; r++) {
        float v = h[(size_t)r * HIDD + c];
        s += v;
        ss = fmaf(v, v, ss);
    }
    atomicAdd(&g_sum[c], s);
    atomicAdd(&g_sumsq[c], ss);
}

__global__ void k_bn_finalize(const float* __restrict__ gamma,
                              const float* __restrict__ beta) {
    int c = threadIdx.x;
    float mu = g_sum[c] * (1.f / NN);
    float var = g_sumsq[c] * (1.f / NN) - mu * mu;
    float rstd = rsqrtf(var + BN_EPS);
    float sc = rstd * gamma[c];
    g_bn_s[c] = sc;
    g_bn_t[c] = beta[c] - mu * sc;
    g_sum[c] = 0.f;
    g_sumsq[c] = 0.f;
}

// ---------------- launch ----------------
extern "C" void kernel_launch(void* const* d_in, const int* in_sizes, int n_in,
                              void* d_out, int out_size) {
    const float* x     = (const float*)d_in[0];
    const void*  ei    = d_in[1];
    const float* W1    = (const float*)d_in[2];
    const float* b1    = (const float*)d_in[3];
    const float* W2    = (const float*)d_in[4];
    const float* b2    = (const float*)d_in[5];
    const float* W3    = (const float*)d_in[6];
    const float* b3    = (const float*)d_in[7];
    const float* gamma = (const float*)d_in[8];
    const float* beta  = (const float*)d_in[9];
    float* out = (float*)d_out;

    float *t1, *t2;
    cudaGetSymbolAddress((void**)&t1, g_t1);
    cudaGetSymbolAddress((void**)&t2, g_t2);

    // preprocessing
    k_convert_deg<<<cdiv(EE, 256), 256>>>(ei);   // 0
    k_scan_dinv<<<1, 1024>>>();                  // 1
    k_fill<<<cdiv(TOT, 256), 256>>>();           // 2

    dim3 g256(4, cdiv(NN, 128));    // Ncols=256
    dim3 g40(1, cdiv(NN, 128));     // Ncols=40

    // layer 1: agg-first (128-wide gather, 4 rows/block), GEMM with fused bias
    k_agg_v<32, 4, false><<<cdiv(NN, 4), 128>>>(x, nullptr, t1);           // 3 <- profiled
    k_gemm_tc<false, true><<<g256, 256>>>(t1, W1, b1, t2, NN, IND, HIDD);  // 4
    k_stats<<<256, HIDD>>>(t2);                                            // 5
    k_bn_finalize<<<1, HIDD>>>(gamma, beta);                               // 6

    // layer 2 (BN+ReLU fused into GEMM A-load), 256-wide agg 2 rows/block
    k_gemm_tc<true, false><<<g256, 256>>>(t2, W2, nullptr, t1, NN, HIDD, HIDD); // 7
    k_agg_v<64, 2, true><<<cdiv(NN, 2), 128>>>(t1, b2, t2);                     // 8
    k_stats<<<256, HIDD>>>(t2);                                                 // 9
    k_bn_finalize<<<1, HIDD>>>(gamma, beta);                                    // 10

    // layer 3: GEMM then fused agg+log_softmax straight to output
    k_gemm_tc<true, false><<<g40, 256>>>(t2, W3, nullptr, t1, NN, HIDD, OUTD);  // 11
    k_agg_softmax<<<cdiv(NN, 4), 128>>>(t1, b3, out);                           // 12
}